// round 1
// baseline (speedup 1.0000x reference)
#include <cuda_runtime.h>
#include <math.h>

// ---------------- problem constants ----------------
#define Bq   8
#define Tt   2048
#define Cc   512
#define Hh   4
#define Kk   512
#define Vv   1024
#define DKk  128
#define DVv  256
#define BT   16384          // Bq*Tt

// ---------------- scratch (device global, no allocs) ----------------
#define OFF_N     0L
#define OFF_R     8388608L
#define OFF_K     16777216L
#define OFF_V     25165824L
#define OFF_WT    41943040L
#define OFF_AT    42991616L
#define OFF_GT    44040192L
#define OFF_D     46137344L
#define OFF_A     54525952L
#define OFF_KK    62914560L
#define OFF_AB    71303168L
#define OFF_GATE  79691776L
#define OFF_O     96468992L
#define OFF_Z     113246208L
#define SCRATCH_TOTAL 130023424L

__device__ __align__(256) float g_scratch[SCRATCH_TOTAL];

// ---------------- LayerNorm over C=512 ----------------
__global__ __launch_bounds__(128) void ln_kernel(
    const float* __restrict__ x, const float* __restrict__ w,
    const float* __restrict__ b, float* __restrict__ outn)
{
    int row = blockIdx.x, tid = threadIdx.x;
    const float4* xr = reinterpret_cast<const float4*>(x + (long)row * Cc);
    float4 xv = xr[tid];
    float s = xv.x + xv.y + xv.z + xv.w;
    float q = xv.x*xv.x + xv.y*xv.y + xv.z*xv.z + xv.w*xv.w;
    #pragma unroll
    for (int o = 16; o; o >>= 1) {
        s += __shfl_xor_sync(0xffffffffu, s, o);
        q += __shfl_xor_sync(0xffffffffu, q, o);
    }
    __shared__ float ss[4], qq[4];
    int wid = tid >> 5;
    if ((tid & 31) == 0) { ss[wid] = s; qq[wid] = q; }
    __syncthreads();
    s = ss[0] + ss[1] + ss[2] + ss[3];
    q = qq[0] + qq[1] + qq[2] + qq[3];
    float mu  = s * (1.0f / Cc);
    float var = q * (1.0f / Cc) - mu * mu;
    float rs  = rsqrtf(var + 1e-5f);
    float4 wv = reinterpret_cast<const float4*>(w)[tid];
    float4 bv = reinterpret_cast<const float4*>(b)[tid];
    float4 ov;
    ov.x = (xv.x - mu) * rs * wv.x + bv.x;
    ov.y = (xv.y - mu) * rs * wv.y + bv.y;
    ov.z = (xv.z - mu) * rs * wv.z + bv.z;
    ov.w = (xv.w - mu) * rs * wv.w + bv.w;
    reinterpret_cast<float4*>(outn + (long)row * Cc)[tid] = ov;
}

// ---------------- general GEMM: out[M,N] = act(A[M,kdim] @ W[kdim,N]) ----------------
// MIXED: A-element = n[row][c] + (n[row-1][c] - n[row][c]) * mix[c]  (zero prev at t==0)
// ACT: 0 none, 1 tanh, 2 sigmoid, 3 decay(bias), 4 sigmoid(bias)
// RESID: out += resid[row*N+col]
#define BMt 128
#define BNt 64
#define BKt 16

template<int ACT, bool MIXED, bool RESID>
__global__ __launch_bounds__(256, 1) void gemm_kernel(
    const float* __restrict__ A, int lda,
    const float* __restrict__ W,
    const float* __restrict__ mixv,
    const float* __restrict__ bias,
    const float* __restrict__ resid,
    float* __restrict__ out, int N, int kdim)
{
    __shared__ float As[2][BKt][BMt];
    __shared__ float Bs[2][BKt][BNt];
    const int tid = threadIdx.x;
    const int m0 = blockIdx.x * BMt;
    const int n0 = blockIdx.y * BNt;
    const int NT = kdim / BKt;

    const int aid0 = tid * 2;
    const int arow0 = aid0 >> 2,       ac0 = aid0 & 3;
    const int arow1 = (aid0 + 1) >> 2, ac1 = (aid0 + 1) & 3;
    const int bkrow = tid >> 4, bc = (tid & 15) * 4;

    float4 areg0, areg1, breg;

    // --- load tile kt into registers ---
    #define LOAD_A_ELT(dst, row_, c4_) do {                                         \
        int grow = m0 + (row_);                                                     \
        int gcol = kt_ld * BKt + (c4_) * 4;                                         \
        float4 nv = *reinterpret_cast<const float4*>(&A[(long)grow * lda + gcol]);  \
        if (MIXED) {                                                                \
            float4 mv = *reinterpret_cast<const float4*>(&mixv[gcol]);              \
            float4 pv = make_float4(0.f, 0.f, 0.f, 0.f);                            \
            if ((grow & (Tt - 1)) != 0)                                             \
                pv = *reinterpret_cast<const float4*>(&A[(long)(grow - 1) * lda + gcol]); \
            nv.x += (pv.x - nv.x) * mv.x;  nv.y += (pv.y - nv.y) * mv.y;            \
            nv.z += (pv.z - nv.z) * mv.z;  nv.w += (pv.w - nv.w) * mv.w;            \
        }                                                                           \
        (dst) = nv;                                                                 \
    } while (0)

    #define LOAD_TILE() do {                                                        \
        LOAD_A_ELT(areg0, arow0, ac0);                                              \
        LOAD_A_ELT(areg1, arow1, ac1);                                              \
        breg = *reinterpret_cast<const float4*>(                                    \
            &W[(long)(kt_ld * BKt + bkrow) * N + n0 + bc]);                         \
    } while (0)

    #define STS_TILE(bufi) do {                                                     \
        As[bufi][ac0 * 4 + 0][arow0] = areg0.x;                                     \
        As[bufi][ac0 * 4 + 1][arow0] = areg0.y;                                     \
        As[bufi][ac0 * 4 + 2][arow0] = areg0.z;                                     \
        As[bufi][ac0 * 4 + 3][arow0] = areg0.w;                                     \
        As[bufi][ac1 * 4 + 0][arow1] = areg1.x;                                     \
        As[bufi][ac1 * 4 + 1][arow1] = areg1.y;                                     \
        As[bufi][ac1 * 4 + 2][arow1] = areg1.z;                                     \
        As[bufi][ac1 * 4 + 3][arow1] = areg1.w;                                     \
        *reinterpret_cast<float4*>(&Bs[bufi][bkrow][bc]) = breg;                    \
    } while (0)

    {
        int kt_ld = 0;
        LOAD_TILE();
    }
    STS_TILE(0);
    __syncthreads();

    const int mb = (tid & 15) * 8;
    const int nb = (tid >> 4) * 4;
    float acc[8][4];
    #pragma unroll
    for (int i = 0; i < 8; i++)
        #pragma unroll
        for (int j = 0; j < 4; j++) acc[i][j] = 0.f;

    for (int kt = 0; kt < NT; kt++) {
        int cur = kt & 1;
        if (kt + 1 < NT) {
            int kt_ld = kt + 1;
            LOAD_TILE();
        }
        #pragma unroll
        for (int kkp = 0; kkp < BKt; kkp++) {
            float4 a0 = *reinterpret_cast<const float4*>(&As[cur][kkp][mb]);
            float4 a1 = *reinterpret_cast<const float4*>(&As[cur][kkp][mb + 4]);
            float4 bb = *reinterpret_cast<const float4*>(&Bs[cur][kkp][nb]);
            float av[8] = {a0.x, a0.y, a0.z, a0.w, a1.x, a1.y, a1.z, a1.w};
            float bv[4] = {bb.x, bb.y, bb.z, bb.w};
            #pragma unroll
            for (int i = 0; i < 8; i++)
                #pragma unroll
                for (int j = 0; j < 4; j++)
                    acc[i][j] = fmaf(av[i], bv[j], acc[i][j]);
        }
        if (kt + 1 < NT) STS_TILE(cur ^ 1);
        __syncthreads();
    }

    #pragma unroll
    for (int i = 0; i < 8; i++) {
        int row = m0 + mb + i;
        float vals[4];
        #pragma unroll
        for (int j = 0; j < 4; j++) {
            float v = acc[i][j];
            int col = n0 + nb + j;
            if (ACT == 1) v = tanhf(v);
            else if (ACT == 2) v = 1.f / (1.f + expf(-v));
            else if (ACT == 3) {
                v += bias[col];
                float w = -log1pf(expf(-v)) - 0.5f;
                v = expf(-expf(w));
            } else if (ACT == 4) {
                v += bias[col];
                v = 1.f / (1.f + expf(-v));
            }
            if (RESID) v += resid[(long)row * N + col];
            vals[j] = v;
        }
        *reinterpret_cast<float4*>(&out[(long)row * N + n0 + nb]) =
            make_float4(vals[0], vals[1], vals[2], vals[3]);
    }
    #undef LOAD_A_ELT
    #undef LOAD_TILE
    #undef STS_TILE
}

// ---------------- mix kernel: kk normalize, k final, ab ----------------
__global__ __launch_bounds__(512) void mix_kernel(
    float* __restrict__ kbuf,            // in: k raw; out: k final (in place)
    const float* __restrict__ abuf,
    float* __restrict__ kkbuf, float* __restrict__ abb,
    const float* __restrict__ k_k, const float* __restrict__ k_a)
{
    int bt = blockIdx.x, c = threadIdx.x;
    long idx = (long)bt * Kk + c;
    float kraw = kbuf[idx];
    float a    = abuf[idx];
    float kkv  = kraw * k_k[c];
    float sq   = kkv * kkv;
    #pragma unroll
    for (int o = 16; o; o >>= 1) sq += __shfl_xor_sync(0xffffffffu, sq, o);
    __shared__ float sm[16];
    int wid = c >> 5;
    if ((c & 31) == 0) sm[wid] = sq;
    __syncthreads();
    int h = c >> 7;
    float tot = sm[h * 4] + sm[h * 4 + 1] + sm[h * 4 + 2] + sm[h * 4 + 3];
    float inv = 1.f / fmaxf(sqrtf(tot), 1e-12f);
    float kkn = kkv * inv;
    kkbuf[idx] = kkn;
    abb[idx]   = kkn * a;
    kbuf[idx]  = kraw * (1.f + (a - 1.f) * k_a[c]);
}

// ---------------- sequential scan ----------------
// grid = Bq*Hh*NSPLIT CTAs; 256 threads; thread (krep=tid&3, vloc=tid>>2)
// owns S[vrow = split*64+vloc][krep*32 .. +32) in 32 registers.
#define NSPLIT 4

__global__ __launch_bounds__(256, 1) void scan_kernel(
    const float* __restrict__ dbuf,  const float* __restrict__ kkbuf,
    const float* __restrict__ abbuf, const float* __restrict__ kfbuf,
    const float* __restrict__ rbuf,  const float* __restrict__ vbuf,
    float* __restrict__ obuf)
{
    int blk   = blockIdx.x;
    int split = blk & (NSPLIT - 1);
    int bh    = blk / NSPLIT;
    int b     = bh >> 2, h = bh & 3;
    int tid   = threadIdx.x;
    int krep  = tid & 3, vloc = tid >> 2;

    // slots(f4): 0-31 kk | 32-63 d | 64-95 ab | 96-127 kf | 128-159 r | 160-175 v
    __shared__ float4 buf[2][176];

    float S[32];
    #pragma unroll
    for (int i = 0; i < 32; i++) S[i] = 0.f;

    long vecb = ((long)b * Tt) * 128 + h * 32;                    // f4 units, stride 128/step
    long vvb  = ((long)b * Tt) * 256 + h * 64 + split * 16;       // f4 units, stride 256/step

    const float4* src = reinterpret_cast<const float4*>(kkbuf) + vecb;  // default
    long stride = 128;
    int  slot = tid;
    bool loader = (tid < 176);
    if (slot < 32)       { src = reinterpret_cast<const float4*>(kkbuf) + vecb + slot;        stride = 128; }
    else if (slot < 64)  { src = reinterpret_cast<const float4*>(dbuf)  + vecb + (slot - 32); stride = 128; }
    else if (slot < 96)  { src = reinterpret_cast<const float4*>(abbuf) + vecb + (slot - 64); stride = 128; }
    else if (slot < 128) { src = reinterpret_cast<const float4*>(kfbuf) + vecb + (slot - 96); stride = 128; }
    else if (slot < 160) { src = reinterpret_cast<const float4*>(rbuf)  + vecb + (slot - 128);stride = 128; }
    else if (slot < 176) { src = reinterpret_cast<const float4*>(vbuf)  + vvb  + (slot - 160);stride = 256; }

    float* obase = obuf + ((long)b * Tt) * Vv + h * DVv + split * 64 + vloc;

    const int kb = krep * 8;
    float4 reg = make_float4(0.f, 0.f, 0.f, 0.f);
    if (loader) reg = *src;

    for (int t = 0; t < Tt; t++) {
        int cur = t & 1;
        if (loader) buf[cur][slot] = reg;
        __syncthreads();
        if (loader && (t + 1 < Tt)) reg = src[(long)(t + 1) * stride];

        const float4* kkb = &buf[cur][0];
        const float4* db  = &buf[cur][32];
        const float4* abp = &buf[cur][64];
        const float4* kfb = &buf[cur][96];
        const float4* rb  = &buf[cur][128];
        const float*  vs  = reinterpret_cast<const float*>(&buf[cur][160]);

        float sa0 = 0.f, sa1 = 0.f;
        #pragma unroll
        for (int j = 0; j < 8; j++) {
            float4 q = kkb[kb + j];
            sa0 = fmaf(S[4*j+0], q.x, sa0);
            sa1 = fmaf(S[4*j+1], q.y, sa1);
            sa0 = fmaf(S[4*j+2], q.z, sa0);
            sa1 = fmaf(S[4*j+3], q.w, sa1);
        }
        float sa = sa0 + sa1;
        sa += __shfl_xor_sync(0xffffffffu, sa, 1);
        sa += __shfl_xor_sync(0xffffffffu, sa, 2);

        float vt = vs[vloc];
        float o0 = 0.f, o1 = 0.f;
        #pragma unroll
        for (int j = 0; j < 8; j++) {
            float4 dq = db[kb + j], aq = abp[kb + j], kq = kfb[kb + j], rq = rb[kb + j];
            float t0;
            t0 = fmaf(vt, kq.x, -sa * aq.x); S[4*j+0] = fmaf(S[4*j+0], dq.x, t0); o0 = fmaf(S[4*j+0], rq.x, o0);
            t0 = fmaf(vt, kq.y, -sa * aq.y); S[4*j+1] = fmaf(S[4*j+1], dq.y, t0); o1 = fmaf(S[4*j+1], rq.y, o1);
            t0 = fmaf(vt, kq.z, -sa * aq.z); S[4*j+2] = fmaf(S[4*j+2], dq.z, t0); o0 = fmaf(S[4*j+2], rq.z, o0);
            t0 = fmaf(vt, kq.w, -sa * aq.w); S[4*j+3] = fmaf(S[4*j+3], dq.w, t0); o1 = fmaf(S[4*j+3], rq.w, o1);
        }
        float o = o0 + o1;
        o += __shfl_xor_sync(0xffffffffu, o, 1);
        o += __shfl_xor_sync(0xffffffffu, o, 2);
        if (krep == 0) obase[(long)t * Vv] = o;
    }
}

// ---------------- groupnorm + bonus + gate ----------------
__global__ __launch_bounds__(256) void post_kernel(
    const float* __restrict__ obuf,  const float* __restrict__ rbuf,
    const float* __restrict__ kfbuf, const float* __restrict__ vbuf,
    const float* __restrict__ gatebuf, const float* __restrict__ rk,
    const float* __restrict__ lnxw, const float* __restrict__ lnxb,
    float* __restrict__ zbuf)
{
    int idx = blockIdx.x;               // bt*H + h
    int bt = idx >> 2, h = idx & 3;
    int v = threadIdx.x;
    long base = (long)bt * Vv + h * DVv;
    float o = obuf[base + v];
    float s = o, q = o * o, bon = 0.f;
    if (v < DKk) {
        long kbi = (long)bt * Kk + h * DKk + v;
        bon = rbuf[kbi] * kfbuf[kbi] * rk[h * DKk + v];
    }
    #pragma unroll
    for (int off = 16; off; off >>= 1) {
        s   += __shfl_xor_sync(0xffffffffu, s, off);
        q   += __shfl_xor_sync(0xffffffffu, q, off);
        bon += __shfl_xor_sync(0xffffffffu, bon, off);
    }
    __shared__ float ss[8], qq[8], bb[8];
    int wid = v >> 5;
    if ((v & 31) == 0) { ss[wid] = s; qq[wid] = q; bb[wid] = bon; }
    __syncthreads();
    s = 0.f; q = 0.f; bon = 0.f;
    #pragma unroll
    for (int i = 0; i < 8; i++) { s += ss[i]; q += qq[i]; bon += bb[i]; }
    float mu  = s * (1.0f / DVv);
    float var = q * (1.0f / DVv) - mu * mu;
    float rs  = rsqrtf(var + 64e-5f);
    float gn  = (o - mu) * rs * lnxw[h * DVv + v] + lnxb[h * DVv + v];
    float val = gn + bon * vbuf[base + v];
    zbuf[base + v] = val * gatebuf[base + v];
}

// ---------------- launcher ----------------
extern "C" void kernel_launch(void* const* d_in, const int* in_sizes, int n_in,
                              void* d_out, int out_size)
{
    (void)in_sizes; (void)n_in; (void)out_size;
    const float* x    = (const float*)d_in[0];
    const float* ln_w = (const float*)d_in[1];
    const float* ln_b = (const float*)d_in[2];
    const float* x_r  = (const float*)d_in[3];
    const float* x_w  = (const float*)d_in[4];
    const float* x_k  = (const float*)d_in[5];
    const float* x_v  = (const float*)d_in[6];
    const float* x_a  = (const float*)d_in[7];
    const float* x_g  = (const float*)d_in[8];
    const float* W_r  = (const float*)d_in[9];
    const float* W_k  = (const float*)d_in[10];
    const float* W_v  = (const float*)d_in[11];
    const float* W_o  = (const float*)d_in[12];
    const float* w0   = (const float*)d_in[13];
    const float* w1   = (const float*)d_in[14];
    const float* w2   = (const float*)d_in[15];
    const float* a0   = (const float*)d_in[16];
    const float* a1   = (const float*)d_in[17];
    const float* a2   = (const float*)d_in[18];
    const float* g1m  = (const float*)d_in[19];
    const float* g2m  = (const float*)d_in[20];
    const float* k_k  = (const float*)d_in[21];
    const float* k_a  = (const float*)d_in[22];
    const float* r_k  = (const float*)d_in[23];
    const float* lnx_w= (const float*)d_in[24];
    const float* lnx_b= (const float*)d_in[25];
    float* out = (float*)d_out;

    float* scr = nullptr;
    cudaGetSymbolAddress((void**)&scr, g_scratch);
    float* n_   = scr + OFF_N;
    float* r_   = scr + OFF_R;
    float* k_   = scr + OFF_K;
    float* v_   = scr + OFF_V;
    float* wt_  = scr + OFF_WT;
    float* at_  = scr + OFF_AT;
    float* gt_  = scr + OFF_GT;
    float* d_   = scr + OFF_D;
    float* a_   = scr + OFF_A;
    float* kk_  = scr + OFF_KK;
    float* ab_  = scr + OFF_AB;
    float* gate_= scr + OFF_GATE;
    float* o_   = scr + OFF_O;
    float* z_   = scr + OFF_Z;

    ln_kernel<<<BT, 128>>>(x, ln_w, ln_b, n_);

    dim3 blk(256);
    dim3 gN512(BT / BMt, 512 / BNt);
    dim3 gN1024(BT / BMt, 1024 / BNt);
    dim3 gN64(BT / BMt, 1);
    dim3 gN128(BT / BMt, 2);

    // token-shift projections (mix fused into A load)
    gemm_kernel<0, true, false><<<gN512, blk>>>(n_, Cc, W_r, x_r, nullptr, nullptr, r_, 512, 512);
    gemm_kernel<0, true, false><<<gN512, blk>>>(n_, Cc, W_k, x_k, nullptr, nullptr, k_, 512, 512);
    gemm_kernel<0, true, false><<<gN1024, blk>>>(n_, Cc, W_v, x_v, nullptr, nullptr, v_, 1024, 512);
    gemm_kernel<1, true, false><<<gN64, blk>>>(n_, Cc, w1, x_w, nullptr, nullptr, wt_, 64, 512);
    gemm_kernel<0, true, false><<<gN64, blk>>>(n_, Cc, a1, x_a, nullptr, nullptr, at_, 64, 512);
    gemm_kernel<2, true, false><<<gN128, blk>>>(n_, Cc, g1m, x_g, nullptr, nullptr, gt_, 128, 512);

    // second-stage LoRA GEMMs with fused epilogues
    gemm_kernel<3, false, false><<<gN512, blk>>>(wt_, 64, w2, nullptr, w0, nullptr, d_, 512, 64);
    gemm_kernel<4, false, false><<<gN512, blk>>>(at_, 64, a2, nullptr, a0, nullptr, a_, 512, 64);
    gemm_kernel<0, false, false><<<gN1024, blk>>>(gt_, 128, g2m, nullptr, nullptr, nullptr, gate_, 1024, 128);

    // kk normalize / k final / ab
    mix_kernel<<<BT, 512>>>(k_, a_, kk_, ab_, k_k, k_a);

    // sequential state scan
    scan_kernel<<<Bq * Hh * NSPLIT, 256>>>(d_, kk_, ab_, k_, r_, v_, o_);

    // groupnorm + bonus + gate
    post_kernel<<<BT * Hh, 256>>>(o_, r_, k_, v_, gate_, r_k, lnx_w, lnx_b, z_);

    // output projection + residual
    gemm_kernel<0, false, true><<<gN512, blk>>>(z_, Vv, W_o, nullptr, nullptr, x, out, 512, 1024);
}

// round 3
// speedup vs baseline: 1.3220x; 1.3220x over previous
#include <cuda_runtime.h>
#include <cuda_bf16.h>
#include <math.h>

// ---------------- problem constants ----------------
#define Bq   8
#define Tt   2048
#define Cc   512
#define Hh   4
#define Kk   512
#define Vv   1024
#define DKk  128
#define DVv  256
#define BT   16384          // Bq*Tt

// ---------------- scratch (device global, no allocs) ----------------
#define OFF_N     0L
#define OFF_R     8388608L
#define OFF_K     16777216L
#define OFF_V     25165824L
#define OFF_WT    41943040L
#define OFF_AT    42991616L
#define OFF_GT    44040192L
#define OFF_D     46137344L
#define OFF_A     54525952L
#define OFF_KK    62914560L
#define OFF_AB    71303168L
#define OFF_GATE  79691776L
#define OFF_O     96468992L
#define OFF_Z     113246208L
#define SCRATCH_TOTAL 130023424L

__device__ __align__(256) float g_scratch[SCRATCH_TOTAL];

__device__ __forceinline__ unsigned smem_u32(const void* p) {
    return (unsigned)__cvta_generic_to_shared(p);
}

// ---------------- LayerNorm over C=512 ----------------
__global__ __launch_bounds__(128) void ln_kernel(
    const float* __restrict__ x, const float* __restrict__ w,
    const float* __restrict__ b, float* __restrict__ outn)
{
    int row = blockIdx.x, tid = threadIdx.x;
    const float4* xr = reinterpret_cast<const float4*>(x + (long)row * Cc);
    float4 xv = xr[tid];
    float s = xv.x + xv.y + xv.z + xv.w;
    float q = xv.x*xv.x + xv.y*xv.y + xv.z*xv.z + xv.w*xv.w;
    #pragma unroll
    for (int o = 16; o; o >>= 1) {
        s += __shfl_xor_sync(0xffffffffu, s, o);
        q += __shfl_xor_sync(0xffffffffu, q, o);
    }
    __shared__ float ss[4], qq[4];
    int wid = tid >> 5;
    if ((tid & 31) == 0) { ss[wid] = s; qq[wid] = q; }
    __syncthreads();
    s = ss[0] + ss[1] + ss[2] + ss[3];
    q = qq[0] + qq[1] + qq[2] + qq[3];
    float mu  = s * (1.0f / Cc);
    float var = q * (1.0f / Cc) - mu * mu;
    float rs  = rsqrtf(var + 1e-5f);
    float4 wv = reinterpret_cast<const float4*>(w)[tid];
    float4 bv = reinterpret_cast<const float4*>(b)[tid];
    float4 ov;
    ov.x = (xv.x - mu) * rs * wv.x + bv.x;
    ov.y = (xv.y - mu) * rs * wv.y + bv.y;
    ov.z = (xv.z - mu) * rs * wv.z + bv.z;
    ov.w = (xv.w - mu) * rs * wv.w + bv.w;
    reinterpret_cast<float4*>(outn + (long)row * Cc)[tid] = ov;
}

// ================= bf16 tensor-core GEMM =================
// out[M,N] = act(A[M,kdim] @ W[kdim,N]) (+resid)
// 128x128 CTA tile, BK=32, 8 warps (2x4), warp tile 64x32, mma m16n8k16.
// ACT: 0 none, 2 sigmoid.

__device__ __forceinline__ void ldsm_x4(unsigned* r, unsigned addr) {
    asm volatile("ldmatrix.sync.aligned.m8n8.x4.shared.b16 {%0,%1,%2,%3}, [%4];\n"
        : "=r"(r[0]), "=r"(r[1]), "=r"(r[2]), "=r"(r[3]) : "r"(addr));
}
__device__ __forceinline__ void ldsm_x4_t(unsigned* r, unsigned addr) {
    asm volatile("ldmatrix.sync.aligned.m8n8.x4.trans.shared.b16 {%0,%1,%2,%3}, [%4];\n"
        : "=r"(r[0]), "=r"(r[1]), "=r"(r[2]), "=r"(r[3]) : "r"(addr));
}
__device__ __forceinline__ void mma_bf16(float* d, const unsigned* a, const unsigned* b) {
    asm("mma.sync.aligned.m16n8k16.row.col.f32.bf16.bf16.f32 "
        "{%0,%1,%2,%3}, {%4,%5,%6,%7}, {%8,%9}, {%0,%1,%2,%3};\n"
        : "+f"(d[0]), "+f"(d[1]), "+f"(d[2]), "+f"(d[3])
        : "r"(a[0]), "r"(a[1]), "r"(a[2]), "r"(a[3]), "r"(b[0]), "r"(b[1]));
}

template<int ACT, bool MIXED, bool RESID>
__global__ __launch_bounds__(256, 1) void hgemm_kernel(
    const float* __restrict__ A, int lda,
    const float* __restrict__ W,
    const float* __restrict__ mixv,
    const float* __restrict__ resid,
    float* __restrict__ out, int N, int kdim)
{
    __shared__ __align__(16) __nv_bfloat16 As[2][128][40];   // pad 32->40: conflict-free ldmatrix
    __shared__ __align__(16) __nv_bfloat16 Bs[2][32][136];   // pad 128->136
    const int tid = threadIdx.x;
    const int m0 = blockIdx.x * 128;
    const int n0 = blockIdx.y * 128;
    const int NT = kdim / 32;

    float4 la[4], lb[4];

    #define H_LOAD(kt_ld) do {                                                        \
        _Pragma("unroll")                                                             \
        for (int i = 0; i < 4; i++) {                                                 \
            int p = tid + 256 * i;                                                    \
            int row = p >> 3, c4 = p & 7;                                             \
            int grow = m0 + row;                                                      \
            int gcol = (kt_ld) * 32 + c4 * 4;                                         \
            float4 nv = *reinterpret_cast<const float4*>(&A[(long)grow * lda + gcol]);\
            if (MIXED) {                                                              \
                float4 mv = *reinterpret_cast<const float4*>(&mixv[gcol]);            \
                float4 pv = make_float4(0.f, 0.f, 0.f, 0.f);                          \
                if ((grow & (Tt - 1)) != 0)                                           \
                    pv = *reinterpret_cast<const float4*>(&A[(long)(grow-1)*lda + gcol]); \
                nv.x += (pv.x - nv.x) * mv.x;  nv.y += (pv.y - nv.y) * mv.y;          \
                nv.z += (pv.z - nv.z) * mv.z;  nv.w += (pv.w - nv.w) * mv.w;          \
            }                                                                         \
            la[i] = nv;                                                               \
        }                                                                             \
        _Pragma("unroll")                                                             \
        for (int i = 0; i < 4; i++) {                                                 \
            int p = tid + 256 * i;                                                    \
            int kr = p >> 5, c4 = p & 31;                                             \
            lb[i] = *reinterpret_cast<const float4*>(                                 \
                &W[(long)((kt_ld) * 32 + kr) * N + n0 + c4 * 4]);                     \
        }                                                                             \
    } while (0)

    #define H_STS(bufi) do {                                                          \
        _Pragma("unroll")                                                             \
        for (int i = 0; i < 4; i++) {                                                 \
            int p = tid + 256 * i;                                                    \
            int row = p >> 3, c4 = p & 7;                                             \
            __nv_bfloat162 p0 = __floats2bfloat162_rn(la[i].x, la[i].y);              \
            __nv_bfloat162 p1 = __floats2bfloat162_rn(la[i].z, la[i].w);              \
            uint2 u; u.x = *reinterpret_cast<unsigned*>(&p0);                         \
            u.y = *reinterpret_cast<unsigned*>(&p1);                                  \
            *reinterpret_cast<uint2*>(&As[bufi][row][c4 * 4]) = u;                    \
        }                                                                             \
        _Pragma("unroll")                                                             \
        for (int i = 0; i < 4; i++) {                                                 \
            int p = tid + 256 * i;                                                    \
            int kr = p >> 5, c4 = p & 31;                                             \
            __nv_bfloat162 p0 = __floats2bfloat162_rn(lb[i].x, lb[i].y);              \
            __nv_bfloat162 p1 = __floats2bfloat162_rn(lb[i].z, lb[i].w);              \
            uint2 u; u.x = *reinterpret_cast<unsigned*>(&p0);                         \
            u.y = *reinterpret_cast<unsigned*>(&p1);                                  \
            *reinterpret_cast<uint2*>(&Bs[bufi][kr][c4 * 4]) = u;                     \
        }                                                                             \
    } while (0)

    H_LOAD(0);
    H_STS(0);
    __syncthreads();

    const int lane = tid & 31;
    const int w    = tid >> 5;
    const int mw   = (w >> 2) * 64;
    const int nw   = (w & 3) * 32;
    const int lrow = (lane & 7) + (lane & 8);
    const int lcol = (lane >> 4) * 8;

    float acc[4][4][4];
    #pragma unroll
    for (int a_ = 0; a_ < 4; a_++)
        #pragma unroll
        for (int b_ = 0; b_ < 4; b_++)
            #pragma unroll
            for (int c_ = 0; c_ < 4; c_++) acc[a_][b_][c_] = 0.f;

    for (int kt = 0; kt < NT; kt++) {
        int cur = kt & 1;
        if (kt + 1 < NT) H_LOAD(kt + 1);

        #pragma unroll
        for (int s = 0; s < 2; s++) {
            int k0 = s * 16;
            unsigned af[4][4], bf[2][4];
            #pragma unroll
            for (int mf = 0; mf < 4; mf++)
                ldsm_x4(af[mf], smem_u32(&As[cur][mw + mf * 16 + lrow][k0 + lcol]));
            #pragma unroll
            for (int nf2 = 0; nf2 < 2; nf2++)
                ldsm_x4_t(bf[nf2], smem_u32(&Bs[cur][k0 + lrow][nw + nf2 * 16 + lcol]));
            #pragma unroll
            for (int mf = 0; mf < 4; mf++)
                #pragma unroll
                for (int nf = 0; nf < 4; nf++)
                    mma_bf16(acc[mf][nf], af[mf], &bf[nf >> 1][(nf & 1) * 2]);
        }

        if (kt + 1 < NT) H_STS(cur ^ 1);
        __syncthreads();
    }

    // epilogue
    const int gr = lane >> 2, gc = (lane & 3) * 2;
    #pragma unroll
    for (int mf = 0; mf < 4; mf++) {
        #pragma unroll
        for (int nf = 0; nf < 4; nf++) {
            int col = n0 + nw + nf * 8 + gc;
            #pragma unroll
            for (int half = 0; half < 2; half++) {
                int row = m0 + mw + mf * 16 + gr + half * 8;
                float v0 = acc[mf][nf][half * 2 + 0];
                float v1 = acc[mf][nf][half * 2 + 1];
                if (ACT == 2) {
                    v0 = 1.f / (1.f + expf(-v0));
                    v1 = 1.f / (1.f + expf(-v1));
                }
                if (RESID) {
                    v0 += resid[(long)row * N + col];
                    v1 += resid[(long)row * N + col + 1];
                }
                *reinterpret_cast<float2*>(&out[(long)row * N + col]) = make_float2(v0, v1);
            }
        }
    }
    #undef H_LOAD
    #undef H_STS
}

// ---------------- fp32 SIMT GEMM (kept for small accuracy-critical LoRA paths) ----------------
// ACT: 0 none, 1 tanh, 3 decay(bias), 4 sigmoid(bias)
#define BMt 128
#define BNt 64
#define BKt 16

template<int ACT, bool MIXED>
__global__ __launch_bounds__(256, 1) void gemm_kernel(
    const float* __restrict__ A, int lda,
    const float* __restrict__ W,
    const float* __restrict__ mixv,
    const float* __restrict__ bias,
    float* __restrict__ out, int N, int kdim)
{
    __shared__ float As[2][BKt][BMt];
    __shared__ float Bs[2][BKt][BNt];
    const int tid = threadIdx.x;
    const int m0 = blockIdx.x * BMt;
    const int n0 = blockIdx.y * BNt;
    const int NT = kdim / BKt;

    const int aid0 = tid * 2;
    const int arow0 = aid0 >> 2,       ac0 = aid0 & 3;
    const int arow1 = (aid0 + 1) >> 2, ac1 = (aid0 + 1) & 3;
    const int bkrow = tid >> 4, bc = (tid & 15) * 4;

    float4 areg0, areg1, breg;

    #define LOAD_A_ELT(dst, row_, c4_) do {                                         \
        int grow = m0 + (row_);                                                     \
        int gcol = kt_ld * BKt + (c4_) * 4;                                         \
        float4 nv = *reinterpret_cast<const float4*>(&A[(long)grow * lda + gcol]);  \
        if (MIXED) {                                                                \
            float4 mv = *reinterpret_cast<const float4*>(&mixv[gcol]);              \
            float4 pv = make_float4(0.f, 0.f, 0.f, 0.f);                            \
            if ((grow & (Tt - 1)) != 0)                                             \
                pv = *reinterpret_cast<const float4*>(&A[(long)(grow - 1) * lda + gcol]); \
            nv.x += (pv.x - nv.x) * mv.x;  nv.y += (pv.y - nv.y) * mv.y;            \
            nv.z += (pv.z - nv.z) * mv.z;  nv.w += (pv.w - nv.w) * mv.w;            \
        }                                                                           \
        (dst) = nv;                                                                 \
    } while (0)

    #define LOAD_TILE() do {                                                        \
        LOAD_A_ELT(areg0, arow0, ac0);                                              \
        LOAD_A_ELT(areg1, arow1, ac1);                                              \
        breg = *reinterpret_cast<const float4*>(                                    \
            &W[(long)(kt_ld * BKt + bkrow) * N + n0 + bc]);                         \
    } while (0)

    #define STS_TILE(bufi) do {                                                     \
        As[bufi][ac0 * 4 + 0][arow0] = areg0.x;                                     \
        As[bufi][ac0 * 4 + 1][arow0] = areg0.y;                                     \
        As[bufi][ac0 * 4 + 2][arow0] = areg0.z;                                     \
        As[bufi][ac0 * 4 + 3][arow0] = areg0.w;                                     \
        As[bufi][ac1 * 4 + 0][arow1] = areg1.x;                                     \
        As[bufi][ac1 * 4 + 1][arow1] = areg1.y;                                     \
        As[bufi][ac1 * 4 + 2][arow1] = areg1.z;                                     \
        As[bufi][ac1 * 4 + 3][arow1] = areg1.w;                                     \
        *reinterpret_cast<float4*>(&Bs[bufi][bkrow][bc]) = breg;                    \
    } while (0)

    {
        int kt_ld = 0;
        LOAD_TILE();
    }
    STS_TILE(0);
    __syncthreads();

    const int mb = (tid & 15) * 8;
    const int nb = (tid >> 4) * 4;
    float acc[8][4];
    #pragma unroll
    for (int i = 0; i < 8; i++)
        #pragma unroll
        for (int j = 0; j < 4; j++) acc[i][j] = 0.f;

    for (int kt = 0; kt < NT; kt++) {
        int cur = kt & 1;
        if (kt + 1 < NT) {
            int kt_ld = kt + 1;
            LOAD_TILE();
        }
        #pragma unroll
        for (int kkp = 0; kkp < BKt; kkp++) {
            float4 a0 = *reinterpret_cast<const float4*>(&As[cur][kkp][mb]);
            float4 a1 = *reinterpret_cast<const float4*>(&As[cur][kkp][mb + 4]);
            float4 bb = *reinterpret_cast<const float4*>(&Bs[cur][kkp][nb]);
            float av[8] = {a0.x, a0.y, a0.z, a0.w, a1.x, a1.y, a1.z, a1.w};
            float bv[4] = {bb.x, bb.y, bb.z, bb.w};
            #pragma unroll
            for (int i = 0; i < 8; i++)
                #pragma unroll
                for (int j = 0; j < 4; j++)
                    acc[i][j] = fmaf(av[i], bv[j], acc[i][j]);
        }
        if (kt + 1 < NT) STS_TILE(cur ^ 1);
        __syncthreads();
    }

    #pragma unroll
    for (int i = 0; i < 8; i++) {
        int row = m0 + mb + i;
        float vals[4];
        #pragma unroll
        for (int j = 0; j < 4; j++) {
            float v = acc[i][j];
            int col = n0 + nb + j;
            if (ACT == 1) v = tanhf(v);
            else if (ACT == 3) {
                v += bias[col];
                float w_ = -log1pf(expf(-v)) - 0.5f;
                v = expf(-expf(w_));
            } else if (ACT == 4) {
                v += bias[col];
                v = 1.f / (1.f + expf(-v));
            }
            vals[j] = v;
        }
        *reinterpret_cast<float4*>(&out[(long)row * N + n0 + nb]) =
            make_float4(vals[0], vals[1], vals[2], vals[3]);
    }
    #undef LOAD_A_ELT
    #undef LOAD_TILE
    #undef STS_TILE
}

// ---------------- mix kernel: kk normalize, k final, ab ----------------
__global__ __launch_bounds__(512) void mix_kernel(
    float* __restrict__ kbuf,
    const float* __restrict__ abuf,
    float* __restrict__ kkbuf, float* __restrict__ abb,
    const float* __restrict__ k_k, const float* __restrict__ k_a)
{
    int bt = blockIdx.x, c = threadIdx.x;
    long idx = (long)bt * Kk + c;
    float kraw = kbuf[idx];
    float a    = abuf[idx];
    float kkv  = kraw * k_k[c];
    float sq   = kkv * kkv;
    #pragma unroll
    for (int o = 16; o; o >>= 1) sq += __shfl_xor_sync(0xffffffffu, sq, o);
    __shared__ float sm[16];
    int wid = c >> 5;
    if ((c & 31) == 0) sm[wid] = sq;
    __syncthreads();
    int h = c >> 7;
    float tot = sm[h * 4] + sm[h * 4 + 1] + sm[h * 4 + 2] + sm[h * 4 + 3];
    float inv = 1.f / fmaxf(sqrtf(tot), 1e-12f);
    float kkn = kkv * inv;
    kkbuf[idx] = kkn;
    abb[idx]   = kkn * a;
    kbuf[idx]  = kraw * (1.f + (a - 1.f) * k_a[c]);
}

// ---------------- sequential scan ----------------
#define NSPLIT 4

__global__ __launch_bounds__(256, 1) void scan_kernel(
    const float* __restrict__ dbuf,  const float* __restrict__ kkbuf,
    const float* __restrict__ abbuf, const float* __restrict__ kfbuf,
    const float* __restrict__ rbuf,  const float* __restrict__ vbuf,
    float* __restrict__ obuf)
{
    int blk   = blockIdx.x;
    int split = blk & (NSPLIT - 1);
    int bh    = blk / NSPLIT;
    int b     = bh >> 2, h = bh & 3;
    int tid   = threadIdx.x;
    int krep  = tid & 3, vloc = tid >> 2;

    __shared__ float4 buf[2][176];

    float S[32];
    #pragma unroll
    for (int i = 0; i < 32; i++) S[i] = 0.f;

    long vecb = ((long)b * Tt) * 128 + h * 32;
    long vvb  = ((long)b * Tt) * 256 + h * 64 + split * 16;

    const float4* src = reinterpret_cast<const float4*>(kkbuf) + vecb;
    long stride = 128;
    int  slot = tid;
    bool loader = (tid < 176);
    if (slot < 32)       { src = reinterpret_cast<const float4*>(kkbuf) + vecb + slot;        stride = 128; }
    else if (slot < 64)  { src = reinterpret_cast<const float4*>(dbuf)  + vecb + (slot - 32); stride = 128; }
    else if (slot < 96)  { src = reinterpret_cast<const float4*>(abbuf) + vecb + (slot - 64); stride = 128; }
    else if (slot < 128) { src = reinterpret_cast<const float4*>(kfbuf) + vecb + (slot - 96); stride = 128; }
    else if (slot < 160) { src = reinterpret_cast<const float4*>(rbuf)  + vecb + (slot - 128);stride = 128; }
    else if (slot < 176) { src = reinterpret_cast<const float4*>(vbuf)  + vvb  + (slot - 160);stride = 256; }

    float* obase = obuf + ((long)b * Tt) * Vv + h * DVv + split * 64 + vloc;

    const int kb = krep * 8;
    float4 reg = make_float4(0.f, 0.f, 0.f, 0.f);
    if (loader) reg = *src;

    for (int t = 0; t < Tt; t++) {
        int cur = t & 1;
        if (loader) buf[cur][slot] = reg;
        __syncthreads();
        if (loader && (t + 1 < Tt)) reg = src[(long)(t + 1) * stride];

        const float4* kkb = &buf[cur][0];
        const float4* db  = &buf[cur][32];
        const float4* abp = &buf[cur][64];
        const float4* kfb = &buf[cur][96];
        const float4* rb  = &buf[cur][128];
        const float*  vs  = reinterpret_cast<const float*>(&buf[cur][160]);

        float sa0 = 0.f, sa1 = 0.f;
        #pragma unroll
        for (int j = 0; j < 8; j++) {
            float4 q = kkb[kb + j];
            sa0 = fmaf(S[4*j+0], q.x, sa0);
            sa1 = fmaf(S[4*j+1], q.y, sa1);
            sa0 = fmaf(S[4*j+2], q.z, sa0);
            sa1 = fmaf(S[4*j+3], q.w, sa1);
        }
        float sa = sa0 + sa1;
        sa += __shfl_xor_sync(0xffffffffu, sa, 1);
        sa += __shfl_xor_sync(0xffffffffu, sa, 2);

        float vt = vs[vloc];
        float o0 = 0.f, o1 = 0.f;
        #pragma unroll
        for (int j = 0; j < 8; j++) {
            float4 dq = db[kb + j], aq = abp[kb + j], kq = kfb[kb + j], rq = rb[kb + j];
            float t0;
            t0 = fmaf(vt, kq.x, -sa * aq.x); S[4*j+0] = fmaf(S[4*j+0], dq.x, t0); o0 = fmaf(S[4*j+0], rq.x, o0);
            t0 = fmaf(vt, kq.y, -sa * aq.y); S[4*j+1] = fmaf(S[4*j+1], dq.y, t0); o1 = fmaf(S[4*j+1], rq.y, o1);
            t0 = fmaf(vt, kq.z, -sa * aq.z); S[4*j+2] = fmaf(S[4*j+2], dq.z, t0); o0 = fmaf(S[4*j+2], rq.z, o0);
            t0 = fmaf(vt, kq.w, -sa * aq.w); S[4*j+3] = fmaf(S[4*j+3], dq.w, t0); o1 = fmaf(S[4*j+3], rq.w, o1);
        }
        float o = o0 + o1;
        o += __shfl_xor_sync(0xffffffffu, o, 1);
        o += __shfl_xor_sync(0xffffffffu, o, 2);
        if (krep == 0) obase[(long)t * Vv] = o;
    }
}

// ---------------- groupnorm + bonus + gate ----------------
__global__ __launch_bounds__(256) void post_kernel(
    const float* __restrict__ obuf,  const float* __restrict__ rbuf,
    const float* __restrict__ kfbuf, const float* __restrict__ vbuf,
    const float* __restrict__ gatebuf, const float* __restrict__ rk,
    const float* __restrict__ lnxw, const float* __restrict__ lnxb,
    float* __restrict__ zbuf)
{
    int idx = blockIdx.x;
    int bt = idx >> 2, h = idx & 3;
    int v = threadIdx.x;
    long base = (long)bt * Vv + h * DVv;
    float o = obuf[base + v];
    float s = o, q = o * o, bon = 0.f;
    if (v < DKk) {
        long kbi = (long)bt * Kk + h * DKk + v;
        bon = rbuf[kbi] * kfbuf[kbi] * rk[h * DKk + v];
    }
    #pragma unroll
    for (int off = 16; off; off >>= 1) {
        s   += __shfl_xor_sync(0xffffffffu, s, off);
        q   += __shfl_xor_sync(0xffffffffu, q, off);
        bon += __shfl_xor_sync(0xffffffffu, bon, off);
    }
    __shared__ float ss[8], qq[8], bb[8];
    int wid = v >> 5;
    if ((v & 31) == 0) { ss[wid] = s; qq[wid] = q; bb[wid] = bon; }
    __syncthreads();
    s = 0.f; q = 0.f; bon = 0.f;
    #pragma unroll
    for (int i = 0; i < 8; i++) { s += ss[i]; q += qq[i]; bon += bb[i]; }
    float mu  = s * (1.0f / DVv);
    float var = q * (1.0f / DVv) - mu * mu;
    float rs  = rsqrtf(var + 64e-5f);
    float gn  = (o - mu) * rs * lnxw[h * DVv + v] + lnxb[h * DVv + v];
    float val = gn + bon * vbuf[base + v];
    zbuf[base + v] = val * gatebuf[base + v];
}

// ---------------- launcher ----------------
extern "C" void kernel_launch(void* const* d_in, const int* in_sizes, int n_in,
                              void* d_out, int out_size)
{
    (void)in_sizes; (void)n_in; (void)out_size;
    const float* x    = (const float*)d_in[0];
    const float* ln_w = (const float*)d_in[1];
    const float* ln_b = (const float*)d_in[2];
    const float* x_r  = (const float*)d_in[3];
    const float* x_w  = (const float*)d_in[4];
    const float* x_k  = (const float*)d_in[5];
    const float* x_v  = (const float*)d_in[6];
    const float* x_a  = (const float*)d_in[7];
    const float* x_g  = (const float*)d_in[8];
    const float* W_r  = (const float*)d_in[9];
    const float* W_k  = (const float*)d_in[10];
    const float* W_v  = (const float*)d_in[11];
    const float* W_o  = (const float*)d_in[12];
    const float* w0   = (const float*)d_in[13];
    const float* w1   = (const float*)d_in[14];
    const float* w2   = (const float*)d_in[15];
    const float* a0   = (const float*)d_in[16];
    const float* a1   = (const float*)d_in[17];
    const float* a2   = (const float*)d_in[18];
    const float* g1m  = (const float*)d_in[19];
    const float* g2m  = (const float*)d_in[20];
    const float* k_k  = (const float*)d_in[21];
    const float* k_a  = (const float*)d_in[22];
    const float* r_k  = (const float*)d_in[23];
    const float* lnx_w= (const float*)d_in[24];
    const float* lnx_b= (const float*)d_in[25];
    float* out = (float*)d_out;

    float* scr = nullptr;
    cudaGetSymbolAddress((void**)&scr, g_scratch);
    float* n_   = scr + OFF_N;
    float* r_   = scr + OFF_R;
    float* k_   = scr + OFF_K;
    float* v_   = scr + OFF_V;
    float* wt_  = scr + OFF_WT;
    float* at_  = scr + OFF_AT;
    float* gt_  = scr + OFF_GT;
    float* d_   = scr + OFF_D;
    float* a_   = scr + OFF_A;
    float* kk_  = scr + OFF_KK;
    float* ab_  = scr + OFF_AB;
    float* gate_= scr + OFF_GATE;
    float* o_   = scr + OFF_O;
    float* z_   = scr + OFF_Z;

    ln_kernel<<<BT, 128>>>(x, ln_w, ln_b, n_);

    dim3 blk(256);
    dim3 hg512(BT / 128, 512 / 128);
    dim3 hg1024(BT / 128, 1024 / 128);
    dim3 hg128(BT / 128, 1);
    dim3 gN64(BT / BMt, 1);

    // token-shift projections (mix fused into A load) — bf16 tensor cores
    hgemm_kernel<0, true, false><<<hg512, blk>>>(n_, Cc, W_r, x_r, nullptr, r_, 512, 512);
    hgemm_kernel<0, true, false><<<hg512, blk>>>(n_, Cc, W_k, x_k, nullptr, k_, 512, 512);
    hgemm_kernel<0, true, false><<<hg1024, blk>>>(n_, Cc, W_v, x_v, nullptr, v_, 1024, 512);
    hgemm_kernel<2, true, false><<<hg128, blk>>>(n_, Cc, g1m, x_g, nullptr, gt_, 128, 512);

    // decay / icl-rate LoRA paths stay fp32 (accuracy-critical, tiny)
    gemm_kernel<1, true><<<gN64, blk>>>(n_, Cc, w1, x_w, nullptr, wt_, 64, 512);
    gemm_kernel<0, true><<<gN64, blk>>>(n_, Cc, a1, x_a, nullptr, at_, 64, 512);
    gemm_kernel<3, false><<<dim3(BT / BMt, 8), blk>>>(wt_, 64, w2, nullptr, w0, d_, 512, 64);
    gemm_kernel<4, false><<<dim3(BT / BMt, 8), blk>>>(at_, 64, a2, nullptr, a0, a_, 512, 64);

    // gate stage2 — bf16 tensor cores
    hgemm_kernel<0, false, false><<<hg1024, blk>>>(gt_, 128, g2m, nullptr, nullptr, gate_, 1024, 128);

    // kk normalize / k final / ab
    mix_kernel<<<BT, 512>>>(k_, a_, kk_, ab_, k_k, k_a);

    // sequential state scan
    scan_kernel<<<Bq * Hh * NSPLIT, 256>>>(d_, kk_, ab_, k_, r_, v_, o_);

    // groupnorm + bonus + gate
    post_kernel<<<BT * Hh, 256>>>(o_, r_, k_, v_, gate_, r_k, lnx_w, lnx_b, z_);

    // output projection + residual — bf16 tensor cores
    hgemm_kernel<0, false, true><<<hg512, blk>>>(z_, Vv, W_o, nullptr, x, out, 512, 1024);
}

// round 4
// speedup vs baseline: 3.6037x; 2.7260x over previous
#include <cuda_runtime.h>
#include <cuda_bf16.h>
#include <math.h>

// ---------------- problem constants ----------------
#define Bq   8
#define Tt   2048
#define Cc   512
#define Hh   4
#define Kk   512
#define Vv   1024
#define DKk  128
#define DVv  256
#define BT   16384          // Bq*Tt

// ---------------- scratch (device global, no allocs) ----------------
#define OFF_N     0L
#define OFF_R     8388608L
#define OFF_K     16777216L
#define OFF_V     25165824L
#define OFF_WT    41943040L
#define OFF_AT    42991616L
#define OFF_GT    44040192L
#define OFF_D     46137344L
#define OFF_A     54525952L
#define OFF_KK    62914560L
#define OFF_AB    71303168L
#define OFF_GATE  79691776L
#define OFF_O     96468992L
#define OFF_Z     113246208L
#define SCRATCH_TOTAL 130023424L

__device__ __align__(256) float g_scratch[SCRATCH_TOTAL];

__device__ __forceinline__ unsigned smem_u32(const void* p) {
    return (unsigned)__cvta_generic_to_shared(p);
}

// ---------------- packed f32x2 helpers ----------------
typedef unsigned long long u64;
__device__ __forceinline__ u64 pk2(float lo, float hi) {
    u64 r; asm("mov.b64 %0,{%1,%2};" : "=l"(r) : "f"(lo), "f"(hi)); return r;
}
__device__ __forceinline__ void upk2(float& lo, float& hi, u64 v) {
    asm("mov.b64 {%0,%1},%2;" : "=f"(lo), "=f"(hi) : "l"(v));
}
__device__ __forceinline__ u64 fma2(u64 a, u64 b, u64 c) {
    u64 d; asm("fma.rn.f32x2 %0,%1,%2,%3;" : "=l"(d) : "l"(a), "l"(b), "l"(c)); return d;
}
__device__ __forceinline__ u64 mul2(u64 a, u64 b) {
    u64 d; asm("mul.rn.f32x2 %0,%1,%2;" : "=l"(d) : "l"(a), "l"(b)); return d;
}

// ---------------- LayerNorm over C=512 ----------------
__global__ __launch_bounds__(128) void ln_kernel(
    const float* __restrict__ x, const float* __restrict__ w,
    const float* __restrict__ b, float* __restrict__ outn)
{
    int row = blockIdx.x, tid = threadIdx.x;
    const float4* xr = reinterpret_cast<const float4*>(x + (long)row * Cc);
    float4 xv = xr[tid];
    float s = xv.x + xv.y + xv.z + xv.w;
    float q = xv.x*xv.x + xv.y*xv.y + xv.z*xv.z + xv.w*xv.w;
    #pragma unroll
    for (int o = 16; o; o >>= 1) {
        s += __shfl_xor_sync(0xffffffffu, s, o);
        q += __shfl_xor_sync(0xffffffffu, q, o);
    }
    __shared__ float ss[4], qq[4];
    int wid = tid >> 5;
    if ((tid & 31) == 0) { ss[wid] = s; qq[wid] = q; }
    __syncthreads();
    s = ss[0] + ss[1] + ss[2] + ss[3];
    q = qq[0] + qq[1] + qq[2] + qq[3];
    float mu  = s * (1.0f / Cc);
    float var = q * (1.0f / Cc) - mu * mu;
    float rs  = rsqrtf(var + 1e-5f);
    float4 wv = reinterpret_cast<const float4*>(w)[tid];
    float4 bv = reinterpret_cast<const float4*>(b)[tid];
    float4 ov;
    ov.x = (xv.x - mu) * rs * wv.x + bv.x;
    ov.y = (xv.y - mu) * rs * wv.y + bv.y;
    ov.z = (xv.z - mu) * rs * wv.z + bv.z;
    ov.w = (xv.w - mu) * rs * wv.w + bv.w;
    reinterpret_cast<float4*>(outn + (long)row * Cc)[tid] = ov;
}

// ================= bf16 tensor-core GEMM =================
__device__ __forceinline__ void ldsm_x4(unsigned* r, unsigned addr) {
    asm volatile("ldmatrix.sync.aligned.m8n8.x4.shared.b16 {%0,%1,%2,%3}, [%4];\n"
        : "=r"(r[0]), "=r"(r[1]), "=r"(r[2]), "=r"(r[3]) : "r"(addr));
}
__device__ __forceinline__ void ldsm_x4_t(unsigned* r, unsigned addr) {
    asm volatile("ldmatrix.sync.aligned.m8n8.x4.trans.shared.b16 {%0,%1,%2,%3}, [%4];\n"
        : "=r"(r[0]), "=r"(r[1]), "=r"(r[2]), "=r"(r[3]) : "r"(addr));
}
__device__ __forceinline__ void mma_bf16(float* d, const unsigned* a, const unsigned* b) {
    asm("mma.sync.aligned.m16n8k16.row.col.f32.bf16.bf16.f32 "
        "{%0,%1,%2,%3}, {%4,%5,%6,%7}, {%8,%9}, {%0,%1,%2,%3};\n"
        : "+f"(d[0]), "+f"(d[1]), "+f"(d[2]), "+f"(d[3])
        : "r"(a[0]), "r"(a[1]), "r"(a[2]), "r"(a[3]), "r"(b[0]), "r"(b[1]));
}

template<int ACT, bool MIXED, bool RESID>
__global__ __launch_bounds__(256, 1) void hgemm_kernel(
    const float* __restrict__ A, int lda,
    const float* __restrict__ W,
    const float* __restrict__ mixv,
    const float* __restrict__ resid,
    float* __restrict__ out, int N, int kdim)
{
    __shared__ __align__(16) __nv_bfloat16 As[2][128][40];
    __shared__ __align__(16) __nv_bfloat16 Bs[2][32][136];
    const int tid = threadIdx.x;
    const int m0 = blockIdx.x * 128;
    const int n0 = blockIdx.y * 128;
    const int NT = kdim / 32;

    float4 la[4], lb[4];

    #define H_LOAD(kt_ld) do {                                                        \
        _Pragma("unroll")                                                             \
        for (int i = 0; i < 4; i++) {                                                 \
            int p = tid + 256 * i;                                                    \
            int row = p >> 3, c4 = p & 7;                                             \
            int grow = m0 + row;                                                      \
            int gcol = (kt_ld) * 32 + c4 * 4;                                         \
            float4 nv = *reinterpret_cast<const float4*>(&A[(long)grow * lda + gcol]);\
            if (MIXED) {                                                              \
                float4 mv = *reinterpret_cast<const float4*>(&mixv[gcol]);            \
                float4 pv = make_float4(0.f, 0.f, 0.f, 0.f);                          \
                if ((grow & (Tt - 1)) != 0)                                           \
                    pv = *reinterpret_cast<const float4*>(&A[(long)(grow-1)*lda + gcol]); \
                nv.x += (pv.x - nv.x) * mv.x;  nv.y += (pv.y - nv.y) * mv.y;          \
                nv.z += (pv.z - nv.z) * mv.z;  nv.w += (pv.w - nv.w) * mv.w;          \
            }                                                                         \
            la[i] = nv;                                                               \
        }                                                                             \
        _Pragma("unroll")                                                             \
        for (int i = 0; i < 4; i++) {                                                 \
            int p = tid + 256 * i;                                                    \
            int kr = p >> 5, c4 = p & 31;                                             \
            lb[i] = *reinterpret_cast<const float4*>(                                 \
                &W[(long)((kt_ld) * 32 + kr) * N + n0 + c4 * 4]);                     \
        }                                                                             \
    } while (0)

    #define H_STS(bufi) do {                                                          \
        _Pragma("unroll")                                                             \
        for (int i = 0; i < 4; i++) {                                                 \
            int p = tid + 256 * i;                                                    \
            int row = p >> 3, c4 = p & 7;                                             \
            __nv_bfloat162 p0 = __floats2bfloat162_rn(la[i].x, la[i].y);              \
            __nv_bfloat162 p1 = __floats2bfloat162_rn(la[i].z, la[i].w);              \
            uint2 u; u.x = *reinterpret_cast<unsigned*>(&p0);                         \
            u.y = *reinterpret_cast<unsigned*>(&p1);                                  \
            *reinterpret_cast<uint2*>(&As[bufi][row][c4 * 4]) = u;                    \
        }                                                                             \
        _Pragma("unroll")                                                             \
        for (int i = 0; i < 4; i++) {                                                 \
            int p = tid + 256 * i;                                                    \
            int kr = p >> 5, c4 = p & 31;                                             \
            __nv_bfloat162 p0 = __floats2bfloat162_rn(lb[i].x, lb[i].y);              \
            __nv_bfloat162 p1 = __floats2bfloat162_rn(lb[i].z, lb[i].w);              \
            uint2 u; u.x = *reinterpret_cast<unsigned*>(&p0);                         \
            u.y = *reinterpret_cast<unsigned*>(&p1);                                  \
            *reinterpret_cast<uint2*>(&Bs[bufi][kr][c4 * 4]) = u;                     \
        }                                                                             \
    } while (0)

    H_LOAD(0);
    H_STS(0);
    __syncthreads();

    const int lane = tid & 31;
    const int w    = tid >> 5;
    const int mw   = (w >> 2) * 64;
    const int nw   = (w & 3) * 32;
    const int lrow = (lane & 7) + (lane & 8);
    const int lcol = (lane >> 4) * 8;

    float acc[4][4][4];
    #pragma unroll
    for (int a_ = 0; a_ < 4; a_++)
        #pragma unroll
        for (int b_ = 0; b_ < 4; b_++)
            #pragma unroll
            for (int c_ = 0; c_ < 4; c_++) acc[a_][b_][c_] = 0.f;

    for (int kt = 0; kt < NT; kt++) {
        int cur = kt & 1;
        if (kt + 1 < NT) H_LOAD(kt + 1);

        #pragma unroll
        for (int s = 0; s < 2; s++) {
            int k0 = s * 16;
            unsigned af[4][4], bf[2][4];
            #pragma unroll
            for (int mf = 0; mf < 4; mf++)
                ldsm_x4(af[mf], smem_u32(&As[cur][mw + mf * 16 + lrow][k0 + lcol]));
            #pragma unroll
            for (int nf2 = 0; nf2 < 2; nf2++)
                ldsm_x4_t(bf[nf2], smem_u32(&Bs[cur][k0 + lrow][nw + nf2 * 16 + lcol]));
            #pragma unroll
            for (int mf = 0; mf < 4; mf++)
                #pragma unroll
                for (int nf = 0; nf < 4; nf++)
                    mma_bf16(acc[mf][nf], af[mf], &bf[nf >> 1][(nf & 1) * 2]);
        }

        if (kt + 1 < NT) H_STS(cur ^ 1);
        __syncthreads();
    }

    const int gr = lane >> 2, gc = (lane & 3) * 2;
    #pragma unroll
    for (int mf = 0; mf < 4; mf++) {
        #pragma unroll
        for (int nf = 0; nf < 4; nf++) {
            int col = n0 + nw + nf * 8 + gc;
            #pragma unroll
            for (int half = 0; half < 2; half++) {
                int row = m0 + mw + mf * 16 + gr + half * 8;
                float v0 = acc[mf][nf][half * 2 + 0];
                float v1 = acc[mf][nf][half * 2 + 1];
                if (ACT == 2) {
                    v0 = 1.f / (1.f + expf(-v0));
                    v1 = 1.f / (1.f + expf(-v1));
                }
                if (RESID) {
                    v0 += resid[(long)row * N + col];
                    v1 += resid[(long)row * N + col + 1];
                }
                *reinterpret_cast<float2*>(&out[(long)row * N + col]) = make_float2(v0, v1);
            }
        }
    }
    #undef H_LOAD
    #undef H_STS
}

// ---------------- fp32 SIMT GEMM (accuracy-critical LoRA paths) ----------------
#define BMt 128
#define BNt 64
#define BKt 16

template<int ACT, bool MIXED>
__global__ __launch_bounds__(256, 1) void gemm_kernel(
    const float* __restrict__ A, int lda,
    const float* __restrict__ W,
    const float* __restrict__ mixv,
    const float* __restrict__ bias,
    float* __restrict__ out, int N, int kdim)
{
    __shared__ float As[2][BKt][BMt];
    __shared__ float Bs[2][BKt][BNt];
    const int tid = threadIdx.x;
    const int m0 = blockIdx.x * BMt;
    const int n0 = blockIdx.y * BNt;
    const int NT = kdim / BKt;

    const int aid0 = tid * 2;
    const int arow0 = aid0 >> 2,       ac0 = aid0 & 3;
    const int arow1 = (aid0 + 1) >> 2, ac1 = (aid0 + 1) & 3;
    const int bkrow = tid >> 4, bc = (tid & 15) * 4;

    float4 areg0, areg1, breg;

    #define LOAD_A_ELT(dst, row_, c4_) do {                                         \
        int grow = m0 + (row_);                                                     \
        int gcol = kt_ld * BKt + (c4_) * 4;                                         \
        float4 nv = *reinterpret_cast<const float4*>(&A[(long)grow * lda + gcol]);  \
        if (MIXED) {                                                                \
            float4 mv = *reinterpret_cast<const float4*>(&mixv[gcol]);              \
            float4 pv = make_float4(0.f, 0.f, 0.f, 0.f);                            \
            if ((grow & (Tt - 1)) != 0)                                             \
                pv = *reinterpret_cast<const float4*>(&A[(long)(grow - 1) * lda + gcol]); \
            nv.x += (pv.x - nv.x) * mv.x;  nv.y += (pv.y - nv.y) * mv.y;            \
            nv.z += (pv.z - nv.z) * mv.z;  nv.w += (pv.w - nv.w) * mv.w;            \
        }                                                                           \
        (dst) = nv;                                                                 \
    } while (0)

    #define LOAD_TILE() do {                                                        \
        LOAD_A_ELT(areg0, arow0, ac0);                                              \
        LOAD_A_ELT(areg1, arow1, ac1);                                              \
        breg = *reinterpret_cast<const float4*>(                                    \
            &W[(long)(kt_ld * BKt + bkrow) * N + n0 + bc]);                         \
    } while (0)

    #define STS_TILE(bufi) do {                                                     \
        As[bufi][ac0 * 4 + 0][arow0] = areg0.x;                                     \
        As[bufi][ac0 * 4 + 1][arow0] = areg0.y;                                     \
        As[bufi][ac0 * 4 + 2][arow0] = areg0.z;                                     \
        As[bufi][ac0 * 4 + 3][arow0] = areg0.w;                                     \
        As[bufi][ac1 * 4 + 0][arow1] = areg1.x;                                     \
        As[bufi][ac1 * 4 + 1][arow1] = areg1.y;                                     \
        As[bufi][ac1 * 4 + 2][arow1] = areg1.z;                                     \
        As[bufi][ac1 * 4 + 3][arow1] = areg1.w;                                     \
        *reinterpret_cast<float4*>(&Bs[bufi][bkrow][bc]) = breg;                    \
    } while (0)

    {
        int kt_ld = 0;
        LOAD_TILE();
    }
    STS_TILE(0);
    __syncthreads();

    const int mb = (tid & 15) * 8;
    const int nb = (tid >> 4) * 4;
    float acc[8][4];
    #pragma unroll
    for (int i = 0; i < 8; i++)
        #pragma unroll
        for (int j = 0; j < 4; j++) acc[i][j] = 0.f;

    for (int kt = 0; kt < NT; kt++) {
        int cur = kt & 1;
        if (kt + 1 < NT) {
            int kt_ld = kt + 1;
            LOAD_TILE();
        }
        #pragma unroll
        for (int kkp = 0; kkp < BKt; kkp++) {
            float4 a0 = *reinterpret_cast<const float4*>(&As[cur][kkp][mb]);
            float4 a1 = *reinterpret_cast<const float4*>(&As[cur][kkp][mb + 4]);
            float4 bb = *reinterpret_cast<const float4*>(&Bs[cur][kkp][nb]);
            float av[8] = {a0.x, a0.y, a0.z, a0.w, a1.x, a1.y, a1.z, a1.w};
            float bv[4] = {bb.x, bb.y, bb.z, bb.w};
            #pragma unroll
            for (int i = 0; i < 8; i++)
                #pragma unroll
                for (int j = 0; j < 4; j++)
                    acc[i][j] = fmaf(av[i], bv[j], acc[i][j]);
        }
        if (kt + 1 < NT) STS_TILE(cur ^ 1);
        __syncthreads();
    }

    #pragma unroll
    for (int i = 0; i < 8; i++) {
        int row = m0 + mb + i;
        float vals[4];
        #pragma unroll
        for (int j = 0; j < 4; j++) {
            float v = acc[i][j];
            int col = n0 + nb + j;
            if (ACT == 1) v = tanhf(v);
            else if (ACT == 3) {
                v += bias[col];
                float w_ = -log1pf(expf(-v)) - 0.5f;
                v = expf(-expf(w_));
            } else if (ACT == 4) {
                v += bias[col];
                v = 1.f / (1.f + expf(-v));
            }
            vals[j] = v;
        }
        *reinterpret_cast<float4*>(&out[(long)row * N + n0 + nb]) =
            make_float4(vals[0], vals[1], vals[2], vals[3]);
    }
    #undef LOAD_A_ELT
    #undef LOAD_TILE
    #undef STS_TILE
}

// ---------------- mix kernel: kk normalize, k final, ab ----------------
__global__ __launch_bounds__(512) void mix_kernel(
    float* __restrict__ kbuf,
    const float* __restrict__ abuf,
    float* __restrict__ kkbuf, float* __restrict__ abb,
    const float* __restrict__ k_k, const float* __restrict__ k_a)
{
    int bt = blockIdx.x, c = threadIdx.x;
    long idx = (long)bt * Kk + c;
    float kraw = kbuf[idx];
    float a    = abuf[idx];
    float kkv  = kraw * k_k[c];
    float sq   = kkv * kkv;
    #pragma unroll
    for (int o = 16; o; o >>= 1) sq += __shfl_xor_sync(0xffffffffu, sq, o);
    __shared__ float sm[16];
    int wid = c >> 5;
    if ((c & 31) == 0) sm[wid] = sq;
    __syncthreads();
    int h = c >> 7;
    float tot = sm[h * 4] + sm[h * 4 + 1] + sm[h * 4 + 2] + sm[h * 4 + 3];
    float inv = 1.f / fmaxf(sqrtf(tot), 1e-12f);
    float kkn = kkv * inv;
    kkbuf[idx] = kkn;
    abb[idx]   = kkn * a;
    kbuf[idx]  = kraw * (1.f + (a - 1.f) * k_a[c]);
}

// ---------------- sequential scan (f32x2, 4-step groups, padded smem) ----------------
// grid = Bq*Hh*NSPLIT; 256 threads; thread (krep=tid&3, vloc=tid>>2)
// owns S[vrow = split*64+vloc][krep*32 .. +32) packed in 16 u64 regs.
// Step buffer layout (float4 units): per k-vector 36 slots with krep-row
// stride 9 (conflict-free); bases: kk 0, d 36, ab 72, kf 108, r 144, v 180.
#define NSPLIT 4
#define GSTEPS 4
#define NGRP   (Tt / GSTEPS)
#define STEPF4 200

__global__ __launch_bounds__(256, 1) void scan_kernel(
    const float* __restrict__ dbuf,  const float* __restrict__ kkbuf,
    const float* __restrict__ abbuf, const float* __restrict__ kfbuf,
    const float* __restrict__ rbuf,  const float* __restrict__ vbuf,
    float* __restrict__ obuf)
{
    int blk   = blockIdx.x;
    int split = blk & (NSPLIT - 1);
    int bh    = blk / NSPLIT;
    int b     = bh >> 2, h = bh & 3;
    int tid   = threadIdx.x;
    int krep  = tid & 3, vloc = tid >> 2;

    __shared__ __align__(16) float4 buf[2][GSTEPS][STEPF4];

    u64 S2[16];
    #pragma unroll
    for (int i = 0; i < 16; i++) S2[i] = 0ull;

    long vecb = ((long)b * Tt) * 128 + h * 32;   // f4 units, stride 128/step
    long vvb  = ((long)b * Tt) * 256 + h * 64 + split * 16;

    const float4* src = nullptr;
    long stride = 128;
    int  slot = 0;
    bool loader = (tid < 176);
    if (tid < 160) {
        int vec = tid >> 5, e = tid & 31;
        slot = vec * 36 + (e >> 3) * 9 + (e & 7);
        const float4* base;
        if      (vec == 0) base = reinterpret_cast<const float4*>(kkbuf);
        else if (vec == 1) base = reinterpret_cast<const float4*>(dbuf);
        else if (vec == 2) base = reinterpret_cast<const float4*>(abbuf);
        else if (vec == 3) base = reinterpret_cast<const float4*>(kfbuf);
        else               base = reinterpret_cast<const float4*>(rbuf);
        src = base + vecb + e;
        stride = 128;
    } else if (tid < 176) {
        slot = 180 + (tid - 160);
        src = reinterpret_cast<const float4*>(vbuf) + vvb + (tid - 160);
        stride = 256;
    }

    float* obase = obuf + ((long)b * Tt) * Vv + h * DVv + split * 64 + vloc;
    const int kb = krep * 9;

    float4 regs[GSTEPS];

    // prologue: group 0 direct, group 1 prefetch
    if (loader) {
        #pragma unroll
        for (int s = 0; s < GSTEPS; s++) regs[s] = src[(long)s * stride];
        #pragma unroll
        for (int s = 0; s < GSTEPS; s++) buf[0][s][slot] = regs[s];
    }
    __syncthreads();
    if (loader) {
        #pragma unroll
        for (int s = 0; s < GSTEPS; s++) regs[s] = src[(long)(GSTEPS + s) * stride];
    }

    for (int g = 0; g < NGRP; g++) {
        int cur = g & 1;
        #pragma unroll
        for (int s = 0; s < GSTEPS; s++) {
            const float4* P = &buf[cur][s][0];

            // sa = S . kk  (packed)
            u64 saa = 0ull, sab = 0ull;
            #pragma unroll
            for (int j = 0; j < 8; j++) {
                ulonglong2 q = *reinterpret_cast<const ulonglong2*>(P + kb + j);
                saa = fma2(S2[2*j],   q.x, saa);
                sab = fma2(S2[2*j+1], q.y, sab);
            }
            float l0, h0, l1, h1;
            upk2(l0, h0, saa); upk2(l1, h1, sab);
            float sa = (l0 + h0) + (l1 + h1);
            sa += __shfl_xor_sync(0xffffffffu, sa, 1);
            sa += __shfl_xor_sync(0xffffffffu, sa, 2);

            float vt = reinterpret_cast<const float*>(P + 180)[vloc];
            u64 nsa2 = pk2(-sa, -sa);
            u64 vt2  = pk2(vt, vt);

            u64 oa = 0ull, ob = 0ull;
            #pragma unroll
            for (int j = 0; j < 8; j++) {
                ulonglong2 dq = *reinterpret_cast<const ulonglong2*>(P +  36 + kb + j);
                ulonglong2 aq = *reinterpret_cast<const ulonglong2*>(P +  72 + kb + j);
                ulonglong2 kq = *reinterpret_cast<const ulonglong2*>(P + 108 + kb + j);
                ulonglong2 rq = *reinterpret_cast<const ulonglong2*>(P + 144 + kb + j);
                u64 t0 = fma2(vt2, kq.x, mul2(nsa2, aq.x));
                S2[2*j] = fma2(S2[2*j], dq.x, t0);
                oa = fma2(S2[2*j], rq.x, oa);
                u64 t1 = fma2(vt2, kq.y, mul2(nsa2, aq.y));
                S2[2*j+1] = fma2(S2[2*j+1], dq.y, t1);
                ob = fma2(S2[2*j+1], rq.y, ob);
            }
            upk2(l0, h0, oa); upk2(l1, h1, ob);
            float o = (l0 + h0) + (l1 + h1);
            o += __shfl_xor_sync(0xffffffffu, o, 1);
            o += __shfl_xor_sync(0xffffffffu, o, 2);
            if (krep == 0) obase[(long)(g * GSTEPS + s) * Vv] = o;
        }

        if (g + 1 < NGRP) {
            if (loader) {
                #pragma unroll
                for (int s = 0; s < GSTEPS; s++) buf[cur ^ 1][s][slot] = regs[s];
            }
            __syncthreads();
            if (loader && (g + 2 < NGRP)) {
                #pragma unroll
                for (int s = 0; s < GSTEPS; s++)
                    regs[s] = src[(long)((g + 2) * GSTEPS + s) * stride];
            }
        }
    }
}

// ---------------- groupnorm + bonus + gate ----------------
__global__ __launch_bounds__(256) void post_kernel(
    const float* __restrict__ obuf,  const float* __restrict__ rbuf,
    const float* __restrict__ kfbuf, const float* __restrict__ vbuf,
    const float* __restrict__ gatebuf, const float* __restrict__ rk,
    const float* __restrict__ lnxw, const float* __restrict__ lnxb,
    float* __restrict__ zbuf)
{
    int idx = blockIdx.x;
    int bt = idx >> 2, h = idx & 3;
    int v = threadIdx.x;
    long base = (long)bt * Vv + h * DVv;
    float o = obuf[base + v];
    float s = o, q = o * o, bon = 0.f;
    if (v < DKk) {
        long kbi = (long)bt * Kk + h * DKk + v;
        bon = rbuf[kbi] * kfbuf[kbi] * rk[h * DKk + v];
    }
    #pragma unroll
    for (int off = 16; off; off >>= 1) {
        s   += __shfl_xor_sync(0xffffffffu, s, off);
        q   += __shfl_xor_sync(0xffffffffu, q, off);
        bon += __shfl_xor_sync(0xffffffffu, bon, off);
    }
    __shared__ float ss[8], qq[8], bb[8];
    int wid = v >> 5;
    if ((v & 31) == 0) { ss[wid] = s; qq[wid] = q; bb[wid] = bon; }
    __syncthreads();
    s = 0.f; q = 0.f; bon = 0.f;
    #pragma unroll
    for (int i = 0; i < 8; i++) { s += ss[i]; q += qq[i]; bon += bb[i]; }
    float mu  = s * (1.0f / DVv);
    float var = q * (1.0f / DVv) - mu * mu;
    float rs  = rsqrtf(var + 64e-5f);
    float gn  = (o - mu) * rs * lnxw[h * DVv + v] + lnxb[h * DVv + v];
    float val = gn + bon * vbuf[base + v];
    zbuf[base + v] = val * gatebuf[base + v];
}

// ---------------- launcher ----------------
extern "C" void kernel_launch(void* const* d_in, const int* in_sizes, int n_in,
                              void* d_out, int out_size)
{
    (void)in_sizes; (void)n_in; (void)out_size;
    const float* x    = (const float*)d_in[0];
    const float* ln_w = (const float*)d_in[1];
    const float* ln_b = (const float*)d_in[2];
    const float* x_r  = (const float*)d_in[3];
    const float* x_w  = (const float*)d_in[4];
    const float* x_k  = (const float*)d_in[5];
    const float* x_v  = (const float*)d_in[6];
    const float* x_a  = (const float*)d_in[7];
    const float* x_g  = (const float*)d_in[8];
    const float* W_r  = (const float*)d_in[9];
    const float* W_k  = (const float*)d_in[10];
    const float* W_v  = (const float*)d_in[11];
    const float* W_o  = (const float*)d_in[12];
    const float* w0   = (const float*)d_in[13];
    const float* w1   = (const float*)d_in[14];
    const float* w2   = (const float*)d_in[15];
    const float* a0   = (const float*)d_in[16];
    const float* a1   = (const float*)d_in[17];
    const float* a2   = (const float*)d_in[18];
    const float* g1m  = (const float*)d_in[19];
    const float* g2m  = (const float*)d_in[20];
    const float* k_k  = (const float*)d_in[21];
    const float* k_a  = (const float*)d_in[22];
    const float* r_k  = (const float*)d_in[23];
    const float* lnx_w= (const float*)d_in[24];
    const float* lnx_b= (const float*)d_in[25];
    float* out = (float*)d_out;

    float* scr = nullptr;
    cudaGetSymbolAddress((void**)&scr, g_scratch);
    float* n_   = scr + OFF_N;
    float* r_   = scr + OFF_R;
    float* k_   = scr + OFF_K;
    float* v_   = scr + OFF_V;
    float* wt_  = scr + OFF_WT;
    float* at_  = scr + OFF_AT;
    float* gt_  = scr + OFF_GT;
    float* d_   = scr + OFF_D;
    float* a_   = scr + OFF_A;
    float* kk_  = scr + OFF_KK;
    float* ab_  = scr + OFF_AB;
    float* gate_= scr + OFF_GATE;
    float* o_   = scr + OFF_O;
    float* z_   = scr + OFF_Z;

    ln_kernel<<<BT, 128>>>(x, ln_w, ln_b, n_);

    dim3 blk(256);
    dim3 hg512(BT / 128, 512 / 128);
    dim3 hg1024(BT / 128, 1024 / 128);
    dim3 hg128(BT / 128, 1);
    dim3 gN64(BT / BMt, 1);

    // token-shift projections (mix fused into A load) — bf16 tensor cores
    hgemm_kernel<0, true, false><<<hg512, blk>>>(n_, Cc, W_r, x_r, nullptr, r_, 512, 512);
    hgemm_kernel<0, true, false><<<hg512, blk>>>(n_, Cc, W_k, x_k, nullptr, k_, 512, 512);
    hgemm_kernel<0, true, false><<<hg1024, blk>>>(n_, Cc, W_v, x_v, nullptr, v_, 1024, 512);
    hgemm_kernel<2, true, false><<<hg128, blk>>>(n_, Cc, g1m, x_g, nullptr, gt_, 128, 512);

    // decay / icl-rate LoRA paths stay fp32 (accuracy-critical, tiny)
    gemm_kernel<1, true><<<gN64, blk>>>(n_, Cc, w1, x_w, nullptr, wt_, 64, 512);
    gemm_kernel<0, true><<<gN64, blk>>>(n_, Cc, a1, x_a, nullptr, at_, 64, 512);
    gemm_kernel<3, false><<<dim3(BT / BMt, 8), blk>>>(wt_, 64, w2, nullptr, w0, d_, 512, 64);
    gemm_kernel<4, false><<<dim3(BT / BMt, 8), blk>>>(at_, 64, a2, nullptr, a0, a_, 512, 64);

    // gate stage2 — bf16 tensor cores
    hgemm_kernel<0, false, false><<<hg1024, blk>>>(gt_, 128, g2m, nullptr, nullptr, gate_, 1024, 128);

    // kk normalize / k final / ab
    mix_kernel<<<BT, 512>>>(k_, a_, kk_, ab_, k_k, k_a);

    // sequential state scan — f32x2 packed, 4-step barrier groups
    scan_kernel<<<Bq * Hh * NSPLIT, 256>>>(d_, kk_, ab_, k_, r_, v_, o_);

    // groupnorm + bonus + gate
    post_kernel<<<BT * Hh, 256>>>(o_, r_, k_, v_, gate_, r_k, lnx_w, lnx_b, z_);

    // output projection + residual — bf16 tensor cores
    hgemm_kernel<0, false, true><<<hg512, blk>>>(z_, Vv, W_o, nullptr, x, out, 512, 1024);
}